// round 9
// baseline (speedup 1.0000x reference)
#include <cuda_runtime.h>
#include <math.h>

#define BB 8
#define SS 256
#define DD 512
#define NNODE 64
#define VV 32000

typedef unsigned long long u64;

// ---------------- scratch (device globals: allocation-free) ----------------
__device__ float g_xg[BB * SS * DD];          // x @ WgX + bg   (4 MB)
__device__ float g_xu[BB * SS * DD];          // x @ WuX + bu   (4 MB)
__device__ float g_H[2][BB * NNODE * DD];     // node state, double buffered (2 MB)
__device__ float g_cons[BB * SS * DD];        // consensus per (b,t)  (4 MB)
__device__ float g_cln[BB * SS * DD];         // layernormed consensus (4 MB)
__device__ unsigned g_bar[BB];                // per-batch inter-CTA barrier counters

// packed fp32x2 FMA (sm_103a FFMA2) — d.lo += a.lo*b.lo; d.hi += a.hi*b.hi
#define FFMA2(d, a, b) asm("fma.rn.f32x2 %0, %1, %2, %0;" : "+l"(d) : "l"(a), "l"(b))

__device__ __forceinline__ float2 u2f(u64 v) {
    float2 r;
    asm("mov.b64 {%0,%1}, %2;" : "=f"(r.x), "=f"(r.y) : "l"(v));
    return r;
}

// ---------------- reset barrier counters (each launch / graph replay) -------
__global__ void reset_kernel() {
    if (threadIdx.x < BB) g_bar[threadIdx.x] = 0u;
}

// ---------------- embed gather + X-projection (runs once) ------------------
__global__ __launch_bounds__(128) void embed_proj_kernel(
    const int* __restrict__ idx, const float* __restrict__ emb,
    const float* __restrict__ Wg, const float* __restrict__ bg,
    const float* __restrict__ Wu, const float* __restrict__ bu)
{
    const int d0 = blockIdx.x * 32;
    const int m0 = blockIdx.y * 64;
    const int tid = threadIdx.x;
    __shared__ int   idxs[64];
    __shared__ float As[64][36];
    __shared__ float Ws[32][68];

    if (tid < 64) idxs[tid] = idx[m0 + tid];
    __syncthreads();

    const int tm = tid >> 4;
    const int tn = tid & 15;
    float acc[8][4];
#pragma unroll
    for (int i = 0; i < 8; i++)
#pragma unroll
        for (int j = 0; j < 4; j++) acc[i][j] = 0.f;

    for (int k0 = 0; k0 < DD; k0 += 32) {
#pragma unroll
        for (int i = 0; i < 4; i++) {
            int s = tid + i * 128; int n = s >> 3; int j4 = s & 7;
            float4 v = *(const float4*)(emb + (size_t)idxs[n] * DD + k0 + 4 * j4);
            *(float4*)&As[n][4 * j4] = v;
        }
#pragma unroll
        for (int i = 0; i < 2; i++) {
            int s = tid + i * 128; int kk = s >> 3; int j4 = s & 7;
            *(float4*)&Ws[kk][4 * j4]      = *(const float4*)(Wg + (size_t)(k0 + kk) * DD + d0 + 4 * j4);
            *(float4*)&Ws[kk][32 + 4 * j4] = *(const float4*)(Wu + (size_t)(k0 + kk) * DD + d0 + 4 * j4);
        }
        __syncthreads();
#pragma unroll
        for (int kk = 0; kk < 32; kk++) {
            float w[4]; *(float4*)w = *(float4*)&Ws[kk][4 * tn];
            float a[8];
#pragma unroll
            for (int i = 0; i < 8; i++) a[i] = As[tm + 8 * i][kk];
#pragma unroll
            for (int i = 0; i < 8; i++)
#pragma unroll
                for (int j = 0; j < 4; j++) acc[i][j] += a[i] * w[j];
        }
        __syncthreads();
    }

    if (tn < 8) {
#pragma unroll
        for (int i = 0; i < 8; i++) {
            int m = m0 + tm + 8 * i;
#pragma unroll
            for (int j = 0; j < 4; j++) {
                int c = d0 + 4 * tn + j;
                g_xg[(size_t)m * DD + c] = acc[i][j] + bg[c];
            }
        }
    } else {
#pragma unroll
        for (int i = 0; i < 8; i++) {
            int m = m0 + tm + 8 * i;
#pragma unroll
            for (int j = 0; j < 4; j++) {
                int c = d0 + 4 * (tn - 8) + j;
                g_xu[(size_t)m * DD + c] = acc[i][j] + bu[c];
            }
        }
    }
}

// ---------------- persistent recurrence kernel ------------------------------
// grid (16 dim-slices, 8 batches), 256 threads, ~192KB dynamic SMEM (1 CTA/SM,
// 128 CTAs co-resident on 148 SMs). Weights live in SMEM across all 256 steps.
// Per-batch 16-CTA barrier via global atomics between steps.
__global__ __launch_bounds__(256, 1) void persist_kernel(
    const float* __restrict__ Wg, const float* __restrict__ Wu,
    const float* __restrict__ nodes)
{
    extern __shared__ float sm[];
    float* Wsm   = sm;                        // [512][68]  g cols 0-31, u cols 32-63
    float* Ak2   = sm + 512 * 68;             // [2][32][136]  H chunk, (a,a)-duplicated
    float* outS  = Ak2 + 2 * 32 * 136;        // [64][68]
    float* cpart = outS + 64 * 68;            // [256]

    const int ds = blockIdx.x, b = blockIdx.y;
    const int d0 = ds * 32;
    const int tid = threadIdx.x;
    const int tm = tid >> 4;         // 0..15 -> 4-node group
    const int tn = tid & 15;         // 0..15 -> 4-col group
    const int nld = tid & 63;        // node index for chunk loads
    const int kg  = (tid >> 6) * 8;  // k offset within chunk for loads

    // ---- one-time: weight slice into SMEM ----
    for (int s = tid; s < 512 * 8; s += 256) {
        int k = s >> 3, j4 = s & 7;
        *(float4*)&Wsm[k * 68 + 4 * j4]      = *(const float4*)(Wg + (size_t)(DD + k) * DD + d0 + 4 * j4);
        *(float4*)&Wsm[k * 68 + 32 + 4 * j4] = *(const float4*)(Wu + (size_t)(DD + k) * DD + d0 + 4 * j4);
    }
    // ---- one-time: init H slice ----
    for (int s = tid; s < 64 * 8; s += 256) {
        int n = s >> 3, j4 = s & 7;
        *(float4*)(g_H[0] + ((size_t)b * NNODE + n) * DD + d0 + 4 * j4) =
            *(const float4*)(nodes + (size_t)n * DD + d0 + 4 * j4);
    }
    // barrier phase 1 (init)
    __syncthreads();
    __threadfence();
    if (tid == 0) {
        atomicAdd(&g_bar[b], 1u);
        while (((volatile unsigned*)g_bar)[b] < 16u) {}
        __threadfence();
    }
    __syncthreads();

    unsigned phase = 2;
    for (int t = 0; t < SS; t++, phase++) {
        const float* Hin  = g_H[t & 1]       + (size_t)b * NNODE * DD;
        float*       Hout = g_H[(t & 1) ^ 1] + (size_t)b * NNODE * DD;

        u64 acc[4][2];
#pragma unroll
        for (int i = 0; i < 4; i++) { acc[i][0] = 0ull; acc[i][1] = 0ull; }

        // prefetch + store chunk 0 (duplicated)
        float4 pa0 = *(const float4*)(Hin + (size_t)nld * DD + kg);
        float4 pa1 = *(const float4*)(Hin + (size_t)nld * DD + kg + 4);
        {
            float* dst = Ak2;
            *(float2*)(dst + (kg + 0) * 136 + 2 * nld) = make_float2(pa0.x, pa0.x);
            *(float2*)(dst + (kg + 1) * 136 + 2 * nld) = make_float2(pa0.y, pa0.y);
            *(float2*)(dst + (kg + 2) * 136 + 2 * nld) = make_float2(pa0.z, pa0.z);
            *(float2*)(dst + (kg + 3) * 136 + 2 * nld) = make_float2(pa0.w, pa0.w);
            *(float2*)(dst + (kg + 4) * 136 + 2 * nld) = make_float2(pa1.x, pa1.x);
            *(float2*)(dst + (kg + 5) * 136 + 2 * nld) = make_float2(pa1.y, pa1.y);
            *(float2*)(dst + (kg + 6) * 136 + 2 * nld) = make_float2(pa1.z, pa1.z);
            *(float2*)(dst + (kg + 7) * 136 + 2 * nld) = make_float2(pa1.w, pa1.w);
        }
        __syncthreads();

        int buf = 0;
        for (int c = 0; c < 16; c++) {
            if (c < 15) {
                pa0 = *(const float4*)(Hin + (size_t)nld * DD + (c + 1) * 32 + kg);
                pa1 = *(const float4*)(Hin + (size_t)nld * DD + (c + 1) * 32 + kg + 4);
            }
            const float* Ab = Ak2 + buf * (32 * 136);
            const float* Wb = Wsm + c * 32 * 68;
#pragma unroll
            for (int kk = 0; kk < 32; kk++) {
                const u64* ap = (const u64*)(Ab + kk * 136 + 8 * tm);
                const u64* wp = (const u64*)(Wb + kk * 68 + 4 * tn);
                u64 w0 = wp[0], w1 = wp[1];
                u64 a0 = ap[0], a1 = ap[1], a2 = ap[2], a3 = ap[3];
                FFMA2(acc[0][0], a0, w0); FFMA2(acc[0][1], a0, w1);
                FFMA2(acc[1][0], a1, w0); FFMA2(acc[1][1], a1, w1);
                FFMA2(acc[2][0], a2, w0); FFMA2(acc[2][1], a2, w1);
                FFMA2(acc[3][0], a3, w0); FFMA2(acc[3][1], a3, w1);
            }
            if (c < 15) {
                float* dst = Ak2 + (buf ^ 1) * (32 * 136);
                *(float2*)(dst + (kg + 0) * 136 + 2 * nld) = make_float2(pa0.x, pa0.x);
                *(float2*)(dst + (kg + 1) * 136 + 2 * nld) = make_float2(pa0.y, pa0.y);
                *(float2*)(dst + (kg + 2) * 136 + 2 * nld) = make_float2(pa0.z, pa0.z);
                *(float2*)(dst + (kg + 3) * 136 + 2 * nld) = make_float2(pa0.w, pa0.w);
                *(float2*)(dst + (kg + 4) * 136 + 2 * nld) = make_float2(pa1.x, pa1.x);
                *(float2*)(dst + (kg + 5) * 136 + 2 * nld) = make_float2(pa1.y, pa1.y);
                *(float2*)(dst + (kg + 6) * 136 + 2 * nld) = make_float2(pa1.z, pa1.z);
                *(float2*)(dst + (kg + 7) * 136 + 2 * nld) = make_float2(pa1.w, pa1.w);
            }
            __syncthreads();
            buf ^= 1;
        }

        // stash GEMM result
#pragma unroll
        for (int i = 0; i < 4; i++) {
            float2 p0 = u2f(acc[i][0]), p1 = u2f(acc[i][1]);
            *(float4*)&outS[(4 * tm + i) * 68 + 4 * tn] = make_float4(p0.x, p0.y, p1.x, p1.y);
        }
        __syncthreads();

        // gating + H update + consensus partial
        const int d   = tid & 31;
        const int grp = tid >> 5;   // 0..7
        const float xgv = g_xg[((size_t)b * SS + t) * DD + d0 + d];
        const float xuv = g_xu[((size_t)b * SS + t) * DD + d0 + d];
        float sum = 0.f;
#pragma unroll
        for (int q = 0; q < 8; q++) {
            int n = grp * 8 + q;
            float gp = outS[n * 68 + d]      + xgv;
            float up = outS[n * 68 + 32 + d] + xuv;
            float gv = 1.f / (1.f + expf(-gp));
            float cv = tanhf(up);
            float h  = Hin[(size_t)n * DD + d0 + d];
            float hn = gv * cv + (1.f - gv) * h;
            Hout[(size_t)n * DD + d0 + d] = hn;
            sum += hn;
        }
        cpart[grp * 32 + d] = sum;
        __syncthreads();
        if (tid < 32) {
            float tot = 0.f;
#pragma unroll
            for (int g = 0; g < 8; g++) tot += cpart[g * 32 + tid];
            g_cons[((size_t)b * SS + t) * DD + d0 + tid] = tot * (1.0f / 64.0f);
        }

        // inter-CTA barrier (per batch, 16 CTAs)
        __syncthreads();
        __threadfence();
        if (tid == 0) {
            atomicAdd(&g_bar[b], 1u);
            unsigned tgt = 16u * phase;
            while (((volatile unsigned*)g_bar)[b] < tgt) {}
            __threadfence();
        }
        __syncthreads();
    }
}

// ---------------- layernorm over consensus rows -----------------------------
__global__ void layernorm_kernel(const float* __restrict__ lnw,
                                 const float* __restrict__ lnb)
{
    const int r = blockIdx.x;
    const int tid = threadIdx.x;
    const float* x = g_cons + (size_t)r * DD;
    float x0 = x[tid], x1 = x[tid + 256];
    __shared__ float red[256];
    red[tid] = x0 + x1;
    __syncthreads();
    for (int s = 128; s > 0; s >>= 1) {
        if (tid < s) red[tid] += red[tid + s];
        __syncthreads();
    }
    float mu = red[0] * (1.f / 512.f);
    __syncthreads();
    float dv0 = x0 - mu, dv1 = x1 - mu;
    red[tid] = dv0 * dv0 + dv1 * dv1;
    __syncthreads();
    for (int s = 128; s > 0; s >>= 1) {
        if (tid < s) red[tid] += red[tid + s];
        __syncthreads();
    }
    float var = red[0] * (1.f / 512.f);
    float rs = rsqrtf(var + 1e-5f);
    g_cln[(size_t)r * DD + tid]       = dv0 * rs * lnw[tid] + lnb[tid];
    g_cln[(size_t)r * DD + tid + 256] = dv1 * rs * lnw[tid + 256] + lnb[tid + 256];
}

// ---------------- logits GEMM: [2048,512] @ [512,32000] + bh (FFMA2) --------
__global__ __launch_bounds__(128) void logits_kernel(
    const float* __restrict__ Wh, const float* __restrict__ bh,
    float* __restrict__ out)
{
    const int v0 = blockIdx.x * 64;
    const int m0 = blockIdx.y * 64;
    const int tid = threadIdx.x;
    __shared__ float As2[32 * 138];   // [kk][2m dup]
    __shared__ float Bs[32 * 68];     // [kk][v]
    const int tm = tid >> 4;
    const int tn = tid & 15;
    u64 acc[8][2];
#pragma unroll
    for (int i = 0; i < 8; i++) { acc[i][0] = 0ull; acc[i][1] = 0ull; }

    float4 pa[4], pb[4];
#pragma unroll
    for (int i = 0; i < 4; i++) {
        int s = tid + i * 128; int n = s >> 3; int j4 = s & 7;
        pa[i] = *(const float4*)(g_cln + (size_t)(m0 + n) * DD + 4 * j4);
    }
#pragma unroll
    for (int i = 0; i < 4; i++) {
        int s = tid + i * 128; int kk = s >> 4; int j4 = s & 15;
        pb[i] = *(const float4*)(Wh + (size_t)kk * VV + v0 + 4 * j4);
    }

    for (int k0 = 0; k0 < DD; k0 += 32) {
#pragma unroll
        for (int i = 0; i < 4; i++) {
            int s = tid + i * 128; int n = s >> 3; int j4 = s & 7;
            *(float2*)&As2[(4 * j4 + 0) * 138 + 2 * n] = make_float2(pa[i].x, pa[i].x);
            *(float2*)&As2[(4 * j4 + 1) * 138 + 2 * n] = make_float2(pa[i].y, pa[i].y);
            *(float2*)&As2[(4 * j4 + 2) * 138 + 2 * n] = make_float2(pa[i].z, pa[i].z);
            *(float2*)&As2[(4 * j4 + 3) * 138 + 2 * n] = make_float2(pa[i].w, pa[i].w);
        }
#pragma unroll
        for (int i = 0; i < 4; i++) {
            int s = tid + i * 128; int kk = s >> 4; int j4 = s & 15;
            *(float4*)&Bs[kk * 68 + 4 * j4] = pb[i];
        }
        __syncthreads();

        const int k1 = k0 + 32;
        if (k1 < DD) {
#pragma unroll
            for (int i = 0; i < 4; i++) {
                int s = tid + i * 128; int n = s >> 3; int j4 = s & 7;
                pa[i] = *(const float4*)(g_cln + (size_t)(m0 + n) * DD + k1 + 4 * j4);
            }
#pragma unroll
            for (int i = 0; i < 4; i++) {
                int s = tid + i * 128; int kk = s >> 4; int j4 = s & 15;
                pb[i] = *(const float4*)(Wh + (size_t)(k1 + kk) * VV + v0 + 4 * j4);
            }
        }

#pragma unroll
        for (int kk = 0; kk < 32; kk++) {
            const u64* wp = (const u64*)(Bs + kk * 68 + 4 * tn);
            u64 w0 = wp[0], w1 = wp[1];
            const float* ar = As2 + kk * 138 + 2 * tm;
#pragma unroll
            for (int i = 0; i < 8; i++) {
                u64 a = *(const u64*)(ar + 16 * i);
                FFMA2(acc[i][0], a, w0);
                FFMA2(acc[i][1], a, w1);
            }
        }
        __syncthreads();
    }

    float4 bias = *(const float4*)(bh + v0 + 4 * tn);
#pragma unroll
    for (int i = 0; i < 8; i++) {
        float2 p0 = u2f(acc[i][0]), p1 = u2f(acc[i][1]);
        float4 o = make_float4(p0.x + bias.x, p0.y + bias.y, p1.x + bias.z, p1.y + bias.w);
        *(float4*)(out + (size_t)(m0 + tm + 8 * i) * VV + v0 + 4 * tn) = o;
    }
}

// ---------------- launch ----------------------------------------------------
extern "C" void kernel_launch(void* const* d_in, const int* in_sizes, int n_in,
                              void* d_out, int out_size) {
    (void)in_sizes; (void)n_in; (void)out_size;
    const int*   idx   = (const int*)  d_in[0];
    const float* emb   = (const float*)d_in[1];
    const float* nodes = (const float*)d_in[2];
    const float* Wg    = (const float*)d_in[3];
    const float* bg    = (const float*)d_in[4];
    const float* Wu    = (const float*)d_in[5];
    const float* bu    = (const float*)d_in[6];
    const float* lnw   = (const float*)d_in[7];
    const float* lnb   = (const float*)d_in[8];
    const float* Wh    = (const float*)d_in[9];
    const float* bh    = (const float*)d_in[10];
    float* out = (float*)d_out;

    const int smem_bytes = (512 * 68 + 2 * 32 * 136 + 64 * 68 + 256) * 4;  // 192512
    cudaFuncSetAttribute(persist_kernel,
                         cudaFuncAttributeMaxDynamicSharedMemorySize, smem_bytes);

    reset_kernel<<<1, 32>>>();
    embed_proj_kernel<<<dim3(16, 32), 128>>>(idx, emb, Wg, bg, Wu, bu);
    persist_kernel<<<dim3(16, 8), 256, smem_bytes>>>(Wg, Wu, nodes);
    layernorm_kernel<<<BB * SS, 256>>>(lnw, lnb);
    logits_kernel<<<dim3(VV / 64, (BB * SS) / 64), 128>>>(Wh, bh, out);
}